// round 11
// baseline (speedup 1.0000x reference)
#include <cuda_runtime.h>
#include <cuda_fp16.h>
#include <math.h>
#include <stdint.h>

// CTRNN B=8192, N=512, K=512, 6 unfolds + 1 precompute GEMM.
// R11: single-pass fp16 HMMA + fp16 P + L2-prefetch of epilogue operands
//      during the MMA mainloop (hides the serialized epilogue DRAM tail).
//   P16 = fp16(inputs @ W_in + bias)    (mode 0)
//   s' = s + 0.1*(tanh(P16 + s@W_rec)-s)  (mode 1, x6; state carried fp32)
// Geometry: CTA 128x128, warp 64x32, 2 CTAs/SM, 3-stage cp.async ring,
// K-chunk 64 (128B rows, XOR swizzle).

#define BB 8192
#define NN 512
#define KK 512

// ---- scratch (device globals; no allocs allowed) ----
__device__ __half g_A16[BB * KK];        // fp16(inputs)
__device__ __half g_S16[2][BB * NN];     // fp16 state operand (ping-pong)
__device__ float  g_S32[2][BB * NN];     // fp32 state (ping-pong)
__device__ __half g_P16[BB * NN];        // fp16 P
__device__ __half g_WtIn16[NN * KK];     // Wt[n][k] = W[k][n]
__device__ __half g_WtRec16[NN * KK];    // Wt[n][k] = W[k+512][n]

// ---- helpers ----
__device__ __forceinline__ uint32_t smem_u32(const void* p) {
    uint32_t a;
    asm("{ .reg .u64 t; cvta.to.shared.u64 t, %1; cvt.u32.u64 %0, t; }" : "=r"(a) : "l"(p));
    return a;
}
__device__ __forceinline__ void cp_async16(uint32_t dst, const void* src) {
    asm volatile("cp.async.cg.shared.global [%0], [%1], 16;" :: "r"(dst), "l"(src));
}
#define CP_COMMIT() asm volatile("cp.async.commit_group;" ::: "memory")
#define CP_WAIT1()  asm volatile("cp.async.wait_group 1;" ::: "memory")
#define CP_WAIT0()  asm volatile("cp.async.wait_group 0;" ::: "memory")

__device__ __forceinline__ void prefetch_l2(const void* p) {
    asm volatile("prefetch.global.L2 [%0];" :: "l"(p));
}
__device__ __forceinline__ void ldm4(uint32_t* r, uint32_t addr) {
    asm volatile("ldmatrix.sync.aligned.m8n8.x4.shared.b16 {%0,%1,%2,%3}, [%4];"
                 : "=r"(r[0]), "=r"(r[1]), "=r"(r[2]), "=r"(r[3]) : "r"(addr));
}
__device__ __forceinline__ void mma16816(float* d, const uint32_t* a, uint32_t b0, uint32_t b1) {
    asm volatile(
        "mma.sync.aligned.m16n8k16.row.col.f32.f16.f16.f32 "
        "{%0,%1,%2,%3}, {%4,%5,%6,%7}, {%8,%9}, {%0,%1,%2,%3};"
        : "+f"(d[0]), "+f"(d[1]), "+f"(d[2]), "+f"(d[3])
        : "r"(a[0]), "r"(a[1]), "r"(a[2]), "r"(a[3]), "r"(b0), "r"(b1));
}

// ---- geometry ----
#define TM 128
#define TN 128
#define TKC 64                 // K-chunk (fp16) = 128B rows
#define NCHUNK (KK / TKC)      // 8
#define NSTAGE 3
// 128B rows, swizzle: quad' = quad ^ (row & 7)
#define TILE_SZ (128 * 128)    // 16384 bytes (A or B tile)
#define BUF_B (2 * TILE_SZ)    // 32768 (A then B)
#define DSMEM (NSTAGE * BUF_B) // 98304

// fill a 128-row x 64-fp16 tile (128B swizzled rows) from [row0..][kc..kc+64)
__device__ __forceinline__ void fill_tile(uint32_t sbase, const __half* g,
                                          int row0, int kc, int tid) {
    #pragma unroll
    for (int c = tid; c < 1024; c += 256) {      // 1024 16B chunks
        int r = c >> 3, q = c & 7;
        uint32_t dst = sbase + (uint32_t)(r * 128 + ((q ^ (r & 7)) * 16));
        cp_async16(dst, g + (size_t)(row0 + r) * 512 + kc + q * 8);
    }
}

__global__ __launch_bounds__(256, 2)
void ctrnn_hmma(const __half* __restrict__ A16,     // GEMM operand [8192,512] fp16
                const __half* __restrict__ Wt16,    // Wt [N][K] fp16
                const __half* __restrict__ P16,     // mode1 in (fp16 P)
                const float* __restrict__ S32in,    // mode1 in (fp32 state)
                const float* __restrict__ bias,     // mode0 in
                __half* __restrict__ P16out,        // mode0 out
                __half* __restrict__ S16out,        // mode1 out (fp16 shadow)
                float* __restrict__ S32out,         // mode1 out (fp32 state)
                float* __restrict__ S32out2,        // optional dup
                int mode)
{
    extern __shared__ char dsm_raw[];
    const uint32_t dsm = smem_u32(dsm_raw);

    const int tid = threadIdx.x;
    const int w = tid >> 5;
    const int lane = tid & 31;
    const int warpM = w >> 2;        // 0..1 (64 rows each)
    const int warpN = w & 3;         // 0..3 (32 cols each)
    const int br = blockIdx.y * TM;
    const int bc = blockIdx.x * TN;

    float acc[4][4][4];
    #pragma unroll
    for (int mi = 0; mi < 4; mi++)
        #pragma unroll
        for (int ni = 0; ni < 4; ni++)
            #pragma unroll
            for (int q = 0; q < 4; q++) acc[mi][ni][q] = 0.0f;

    // per-lane swizzled ldmatrix base offsets (k16 group g => XOR g*32)
    uint32_t abase[4], bbase[2];
    {
        const int arl = lane & 15, aq = lane >> 4;
        #pragma unroll
        for (int mi = 0; mi < 4; mi++) {
            int row = warpM * 64 + mi * 16 + arl;
            abase[mi] = (uint32_t)(row * 128 + ((aq ^ (row & 7)) * 16));
        }
        const int brl = (lane >> 4) * 8 + (lane & 7), bq = (lane >> 3) & 1;
        #pragma unroll
        for (int p = 0; p < 2; p++) {
            int row = warpN * 32 + p * 16 + brl;
            bbase[p] = (uint32_t)(row * 128 + ((bq ^ (row & 7)) * 16));
        }
    }

    // prologue: fill stages 0,1 (chunks 0,1)
    #pragma unroll
    for (int s = 0; s < 2; s++) {
        uint32_t sb = dsm + s * BUF_B;
        fill_tile(sb,           A16,  br, s * TKC, tid);
        fill_tile(sb + TILE_SZ, Wt16, bc, s * TKC, tid);
        CP_COMMIT();
    }

    int stage = 0, fstage = 2;
    for (int i = 0; i < NCHUNK; i++) {
        if (i == NCHUNK - 1) { CP_WAIT0(); } else { CP_WAIT1(); }
        __syncthreads();     // also guards reuse of stage fstage
        if (i + 2 < NCHUNK) {
            uint32_t nb = dsm + fstage * BUF_B;
            fill_tile(nb,           A16,  br, (i + 2) * TKC, tid);
            fill_tile(nb + TILE_SZ, Wt16, bc, (i + 2) * TKC, tid);
            CP_COMMIT();
        }

        // L2-prefetch this CTA's epilogue operands during the MMA window.
        // P16 block: 128 rows x 256B = 256 lines; S32 block: 128 x 512B = 512
        // lines; 768 total, spread across 8 iterations (256 threads/iter).
        if (mode == 1) {
            int idx = i * 256 + tid;
            if (idx < 256) {
                int r = idx >> 1, l = idx & 1;
                prefetch_l2(P16 + (size_t)(br + r) * 512 + bc + l * 64);
            } else if (idx < 768) {
                int j = idx - 256;
                int r = j >> 2, l = j & 3;
                prefetch_l2(S32in + (size_t)(br + r) * 512 + bc + l * 32);
            }
        }

        const uint32_t sb = dsm + stage * BUF_B;
        #pragma unroll
        for (int g = 0; g < 4; g++) {
            const uint32_t kx = (uint32_t)(g * 32);
            uint32_t a[4][4], b[2][4];
            #pragma unroll
            for (int mi = 0; mi < 4; mi++)
                ldm4(a[mi], (sb + abase[mi]) ^ kx);
            #pragma unroll
            for (int p = 0; p < 2; p++)
                ldm4(b[p], (sb + TILE_SZ + bbase[p]) ^ kx);
            #pragma unroll
            for (int mi = 0; mi < 4; mi++)
                #pragma unroll
                for (int ni = 0; ni < 4; ni++) {
                    const uint32_t* B = b[ni >> 1];
                    const int o = (ni & 1) * 2;
                    mma16816(acc[mi][ni], a[mi], B[o], B[o + 1]);
                }
        }
        stage = (stage + 1 == NSTAGE) ? 0 : stage + 1;
        fstage = (fstage + 1 == NSTAGE) ? 0 : fstage + 1;
    }

    // ---- fused epilogue ----
    const int tg = lane >> 2;        // 0..7
    const int tp = lane & 3;         // 0..3
    const int row0 = br + warpM * 64;
    const int col0 = bc + warpN * 32;

    #pragma unroll
    for (int mi = 0; mi < 4; mi++) {
        #pragma unroll
        for (int h = 0; h < 2; h++) {
            const int r = row0 + mi * 16 + tg + h * 8;
            #pragma unroll
            for (int ni = 0; ni < 4; ni++) {
                const int c = col0 + ni * 8 + tp * 2;
                const size_t off = (size_t)r * NN + c;
                float v0 = acc[mi][ni][h * 2 + 0];
                float v1 = acc[mi][ni][h * 2 + 1];
                if (mode == 0) {
                    float2 bv = *(const float2*)&bias[c];
                    __half2 hp;
                    hp.x = __float2half(v0 + bv.x);
                    hp.y = __float2half(v1 + bv.y);
                    *(__half2*)(P16out + off) = hp;
                } else {
                    __half2 ph = *(const __half2*)(P16 + off);
                    float2 sv = *(const float2*)&S32in[off];
                    float f0 = tanhf(__half2float(ph.x) + v0);
                    float f1 = tanhf(__half2float(ph.y) + v1);
                    float ns0 = sv.x + 0.1f * (f0 - sv.x);
                    float ns1 = sv.y + 0.1f * (f1 - sv.y);
                    *(float2*)&S32out[off] = make_float2(ns0, ns1);
                    __half2 hs;
                    hs.x = __float2half(ns0);
                    hs.y = __float2half(ns1);
                    *(__half2*)(S16out + off) = hs;
                    if (S32out2) *(float2*)&S32out2[off] = make_float2(ns0, ns1);
                }
            }
        }
    }
}

// ---- prep: fp32 -> fp16 for inputs and state ----
#define SPLIT_VECS (BB * KK / 4)

__global__ void split_kernel(const float* __restrict__ in, const float* __restrict__ st,
                             __half* __restrict__ a16, __half* __restrict__ s16)
{
    int t = blockIdx.x * blockDim.x + threadIdx.x;
    if (t >= SPLIT_VECS) return;
    size_t i = (size_t)t * 4;
    float4 vi = *(const float4*)&in[i];
    float4 vs = *(const float4*)&st[i];
    __half2 a0, a1, s0, s1;
    a0.x = __float2half(vi.x); a0.y = __float2half(vi.y);
    a1.x = __float2half(vi.z); a1.y = __float2half(vi.w);
    s0.x = __float2half(vs.x); s0.y = __float2half(vs.y);
    s1.x = __float2half(vs.z); s1.y = __float2half(vs.w);
    *(__half2*)(a16 + i)     = a0;
    *(__half2*)(a16 + i + 2) = a1;
    *(__half2*)(s16 + i)     = s0;
    *(__half2*)(s16 + i + 2) = s1;
}

// ---- prep: transpose W -> Wt[n][k] fp16 (both halves) ----
__global__ void wprep_kernel(const float* __restrict__ W,
                             __half* __restrict__ WtIn, __half* __restrict__ WtRec)
{
    int t = blockIdx.x * blockDim.x + threadIdx.x;
    if (t >= NN * KK) return;
    int k = t / NN, n = t % NN;
    int h = blockIdx.y;
    float v = W[(size_t)(k + h * KK) * NN + n];
    size_t o = (size_t)n * KK + k;
    if (h == 0) WtIn[o]  = __float2half(v);
    else        WtRec[o] = __float2half(v);
}

extern "C" void kernel_launch(void* const* d_in, const int* in_sizes, int n_in,
                              void* d_out, int out_size)
{
    const float* inputs = (const float*)d_in[0];
    const float* state  = (const float*)d_in[1];
    const float* W      = (const float*)d_in[2];
    const float* bias   = (const float*)d_in[3];
    float* out = (float*)d_out;
    float* out2 = (out_size >= 2 * BB * NN) ? (out + (size_t)BB * NN) : nullptr;

    __half *a16, *s16_0, *s16_1, *wtin, *wtrec, *p16;
    float *s32_0, *s32_1;
    cudaGetSymbolAddress((void**)&a16,   g_A16);
    cudaGetSymbolAddress((void**)&s16_0, g_S16);  s16_1 = s16_0 + (size_t)BB * NN;
    cudaGetSymbolAddress((void**)&s32_0, g_S32);  s32_1 = s32_0 + (size_t)BB * NN;
    cudaGetSymbolAddress((void**)&p16,   g_P16);
    cudaGetSymbolAddress((void**)&wtin,  g_WtIn16);
    cudaGetSymbolAddress((void**)&wtrec, g_WtRec16);

    cudaFuncSetAttribute(ctrnn_hmma, cudaFuncAttributeMaxDynamicSharedMemorySize, DSMEM);

    split_kernel<<<(SPLIT_VECS + 255) / 256, 256>>>(inputs, state, a16, s16_0);
    wprep_kernel<<<dim3((NN * KK + 255) / 256, 2), 256>>>(W, wtin, wtrec);

    dim3 grid(NN / TN, BB / TM);   // (4, 64) = 256 CTAs

    // P16 = fp16(inputs @ W_in + bias)
    ctrnn_hmma<<<grid, 256, DSMEM>>>(a16, wtin, nullptr, nullptr, bias, p16,
                                     nullptr, nullptr, nullptr, 0);
    // 6 unfolds: fp16 operand ping-pong, fp32 state ping-pong
    ctrnn_hmma<<<grid, 256, DSMEM>>>(s16_0, wtrec, p16, state, nullptr, nullptr,
                                     s16_1, s32_0, nullptr, 1);
    ctrnn_hmma<<<grid, 256, DSMEM>>>(s16_1, wtrec, p16, s32_0, nullptr, nullptr,
                                     s16_0, s32_1, nullptr, 1);
    ctrnn_hmma<<<grid, 256, DSMEM>>>(s16_0, wtrec, p16, s32_1, nullptr, nullptr,
                                     s16_1, s32_0, nullptr, 1);
    ctrnn_hmma<<<grid, 256, DSMEM>>>(s16_1, wtrec, p16, s32_0, nullptr, nullptr,
                                     s16_0, s32_1, nullptr, 1);
    ctrnn_hmma<<<grid, 256, DSMEM>>>(s16_0, wtrec, p16, s32_1, nullptr, nullptr,
                                     s16_1, s32_0, nullptr, 1);
    ctrnn_hmma<<<grid, 256, DSMEM>>>(s16_1, wtrec, p16, s32_0, nullptr, nullptr,
                                     s16_0, out, out2, 1);
}

// round 12
// speedup vs baseline: 1.1176x; 1.1176x over previous
#include <cuda_runtime.h>
#include <cuda_fp16.h>
#include <math.h>
#include <stdint.h>

// CTRNN B=8192, N=512, K=512, 6 unfolds + 1 precompute GEMM.
// R12: single-pass fp16 HMMA + fp16 P + SMEM-STAGED COALESCED EPILOGUE.
//   The R10/R11 epilogue was LSU-bound (8 lines touched per warp store).
//   Now: acc -> smem staging -> linear float4 pass, all global accesses
//   coalesced. No prefetch (R11 showed it hurts).
// Geometry: CTA 128x128, warp 64x32, 2 CTAs/SM, 3-stage cp.async ring,
// K-chunk 64 (128B rows, XOR swizzle).

#define BB 8192
#define NN 512
#define KK 512

// ---- scratch (device globals; no allocs allowed) ----
__device__ __half g_A16[BB * KK];        // fp16(inputs)
__device__ __half g_S16[2][BB * NN];     // fp16 state operand (ping-pong)
__device__ float  g_S32[2][BB * NN];     // fp32 state (ping-pong)
__device__ __half g_P16[BB * NN];        // fp16 P
__device__ __half g_WtIn16[NN * KK];     // Wt[n][k] = W[k][n]
__device__ __half g_WtRec16[NN * KK];    // Wt[n][k] = W[k+512][n]

// ---- helpers ----
__device__ __forceinline__ uint32_t smem_u32(const void* p) {
    uint32_t a;
    asm("{ .reg .u64 t; cvta.to.shared.u64 t, %1; cvt.u32.u64 %0, t; }" : "=r"(a) : "l"(p));
    return a;
}
__device__ __forceinline__ void cp_async16(uint32_t dst, const void* src) {
    asm volatile("cp.async.cg.shared.global [%0], [%1], 16;" :: "r"(dst), "l"(src));
}
#define CP_COMMIT() asm volatile("cp.async.commit_group;" ::: "memory")
#define CP_WAIT1()  asm volatile("cp.async.wait_group 1;" ::: "memory")
#define CP_WAIT0()  asm volatile("cp.async.wait_group 0;" ::: "memory")

__device__ __forceinline__ void ldm4(uint32_t* r, uint32_t addr) {
    asm volatile("ldmatrix.sync.aligned.m8n8.x4.shared.b16 {%0,%1,%2,%3}, [%4];"
                 : "=r"(r[0]), "=r"(r[1]), "=r"(r[2]), "=r"(r[3]) : "r"(addr));
}
__device__ __forceinline__ void mma16816(float* d, const uint32_t* a, uint32_t b0, uint32_t b1) {
    asm volatile(
        "mma.sync.aligned.m16n8k16.row.col.f32.f16.f16.f32 "
        "{%0,%1,%2,%3}, {%4,%5,%6,%7}, {%8,%9}, {%0,%1,%2,%3};"
        : "+f"(d[0]), "+f"(d[1]), "+f"(d[2]), "+f"(d[3])
        : "r"(a[0]), "r"(a[1]), "r"(a[2]), "r"(a[3]), "r"(b0), "r"(b1));
}

// ---- geometry ----
#define TM 128
#define TN 128
#define TKC 64                 // K-chunk (fp16) = 128B rows
#define NCHUNK (KK / TKC)      // 8
#define NSTAGE 3
#define TILE_SZ (128 * 128)    // 16384 bytes (A or B tile)
#define BUF_B (2 * TILE_SZ)    // 32768 (A then B)
#define STG_STRIDE 132         // floats per staged row (pad vs bank conflicts)
#define DSMEM_MAIN (NSTAGE * BUF_B)              // 98304
#define DSMEM_STG  (TM * STG_STRIDE * 4)         // 67584
#define DSMEM (DSMEM_MAIN > DSMEM_STG ? DSMEM_MAIN : DSMEM_STG)

// fill a 128-row x 64-fp16 tile (128B swizzled rows) from [row0..][kc..kc+64)
__device__ __forceinline__ void fill_tile(uint32_t sbase, const __half* g,
                                          int row0, int kc, int tid) {
    #pragma unroll
    for (int c = tid; c < 1024; c += 256) {      // 1024 16B chunks
        int r = c >> 3, q = c & 7;
        uint32_t dst = sbase + (uint32_t)(r * 128 + ((q ^ (r & 7)) * 16));
        cp_async16(dst, g + (size_t)(row0 + r) * 512 + kc + q * 8);
    }
}

__global__ __launch_bounds__(256, 2)
void ctrnn_hmma(const __half* __restrict__ A16,     // GEMM operand [8192,512] fp16
                const __half* __restrict__ Wt16,    // Wt [N][K] fp16
                const __half* __restrict__ P16,     // mode1 in (fp16 P)
                const float* __restrict__ S32in,    // mode1 in (fp32 state)
                const float* __restrict__ bias,     // mode0 in
                __half* __restrict__ P16out,        // mode0 out
                __half* __restrict__ S16out,        // mode1 out (fp16 shadow; may be null)
                float* __restrict__ S32out,         // mode1 out (fp32 state)
                float* __restrict__ S32out2,        // optional dup
                int mode)
{
    extern __shared__ char dsm_raw[];
    const uint32_t dsm = smem_u32(dsm_raw);
    float* const stg = (float*)dsm_raw;

    const int tid = threadIdx.x;
    const int w = tid >> 5;
    const int lane = tid & 31;
    const int warpM = w >> 2;        // 0..1 (64 rows each)
    const int warpN = w & 3;         // 0..3 (32 cols each)
    const int br = blockIdx.y * TM;
    const int bc = blockIdx.x * TN;

    float acc[4][4][4];
    #pragma unroll
    for (int mi = 0; mi < 4; mi++)
        #pragma unroll
        for (int ni = 0; ni < 4; ni++)
            #pragma unroll
            for (int q = 0; q < 4; q++) acc[mi][ni][q] = 0.0f;

    // per-lane swizzled ldmatrix base offsets (k16 group g => XOR g*32)
    uint32_t abase[4], bbase[2];
    {
        const int arl = lane & 15, aq = lane >> 4;
        #pragma unroll
        for (int mi = 0; mi < 4; mi++) {
            int row = warpM * 64 + mi * 16 + arl;
            abase[mi] = (uint32_t)(row * 128 + ((aq ^ (row & 7)) * 16));
        }
        const int brl = (lane >> 4) * 8 + (lane & 7), bq = (lane >> 3) & 1;
        #pragma unroll
        for (int p = 0; p < 2; p++) {
            int row = warpN * 32 + p * 16 + brl;
            bbase[p] = (uint32_t)(row * 128 + ((bq ^ (row & 7)) * 16));
        }
    }

    // prologue: fill stages 0,1 (chunks 0,1)
    #pragma unroll
    for (int s = 0; s < 2; s++) {
        uint32_t sb = dsm + s * BUF_B;
        fill_tile(sb,           A16,  br, s * TKC, tid);
        fill_tile(sb + TILE_SZ, Wt16, bc, s * TKC, tid);
        CP_COMMIT();
    }

    int stage = 0, fstage = 2;
    for (int i = 0; i < NCHUNK; i++) {
        if (i == NCHUNK - 1) { CP_WAIT0(); } else { CP_WAIT1(); }
        __syncthreads();     // also guards reuse of stage fstage
        if (i + 2 < NCHUNK) {
            uint32_t nb = dsm + fstage * BUF_B;
            fill_tile(nb,           A16,  br, (i + 2) * TKC, tid);
            fill_tile(nb + TILE_SZ, Wt16, bc, (i + 2) * TKC, tid);
            CP_COMMIT();
        }

        const uint32_t sb = dsm + stage * BUF_B;
        #pragma unroll
        for (int g = 0; g < 4; g++) {
            const uint32_t kx = (uint32_t)(g * 32);
            uint32_t a[4][4], b[2][4];
            #pragma unroll
            for (int mi = 0; mi < 4; mi++)
                ldm4(a[mi], (sb + abase[mi]) ^ kx);
            #pragma unroll
            for (int p = 0; p < 2; p++)
                ldm4(b[p], (sb + TILE_SZ + bbase[p]) ^ kx);
            #pragma unroll
            for (int mi = 0; mi < 4; mi++)
                #pragma unroll
                for (int ni = 0; ni < 4; ni++) {
                    const uint32_t* B = b[ni >> 1];
                    const int o = (ni & 1) * 2;
                    mma16816(acc[mi][ni], a[mi], B[o], B[o + 1]);
                }
        }
        stage = (stage + 1 == NSTAGE) ? 0 : stage + 1;
        fstage = (fstage + 1 == NSTAGE) ? 0 : fstage + 1;
    }

    // ---- epilogue: stage acc to smem, then coalesced linear pass ----
    __syncthreads();   // mainloop smem reads complete before overwrite

    const int tg = lane >> 2;        // 0..7
    const int tp = lane & 3;         // 0..3
    #pragma unroll
    for (int mi = 0; mi < 4; mi++) {
        #pragma unroll
        for (int h = 0; h < 2; h++) {
            const int r = warpM * 64 + mi * 16 + tg + h * 8;
            #pragma unroll
            for (int ni = 0; ni < 4; ni++) {
                const int c = warpN * 32 + ni * 8 + tp * 2;
                *(float2*)&stg[r * STG_STRIDE + c] =
                    make_float2(acc[mi][ni][h * 2 + 0], acc[mi][ni][h * 2 + 1]);
            }
        }
    }
    __syncthreads();

    // linear pass: 16384 elems = 4096 float4 chunks; 16 per thread.
    #pragma unroll
    for (int it = 0; it < 16; it++) {
        const int idx = it * 256 + tid;
        const int r = idx >> 5;                // 32 chunks per row
        const int cq = (idx & 31) * 4;
        const float4 v = *(const float4*)&stg[r * STG_STRIDE + cq];
        const size_t off = (size_t)(br + r) * NN + bc + cq;

        if (mode == 0) {
            float4 bv = *(const float4*)&bias[bc + cq];
            __half2 h0, h1;
            h0.x = __float2half(v.x + bv.x); h0.y = __float2half(v.y + bv.y);
            h1.x = __float2half(v.z + bv.z); h1.y = __float2half(v.w + bv.w);
            uint2 o;
            o.x = *(uint32_t*)&h0; o.y = *(uint32_t*)&h1;
            *(uint2*)(P16out + off) = o;
        } else {
            uint2 praw = *(const uint2*)(P16 + off);
            __half2 p0 = *(__half2*)&praw.x, p1 = *(__half2*)&praw.y;
            float4 sv = *(const float4*)&S32in[off];
            float f0 = tanhf(__half2float(p0.x) + v.x);
            float f1 = tanhf(__half2float(p0.y) + v.y);
            float f2 = tanhf(__half2float(p1.x) + v.z);
            float f3 = tanhf(__half2float(p1.y) + v.w);
            float4 ns;
            ns.x = sv.x + 0.1f * (f0 - sv.x);
            ns.y = sv.y + 0.1f * (f1 - sv.y);
            ns.z = sv.z + 0.1f * (f2 - sv.z);
            ns.w = sv.w + 0.1f * (f3 - sv.w);
            *(float4*)&S32out[off] = ns;
            if (S16out) {
                __half2 h0, h1;
                h0.x = __float2half(ns.x); h0.y = __float2half(ns.y);
                h1.x = __float2half(ns.z); h1.y = __float2half(ns.w);
                uint2 o;
                o.x = *(uint32_t*)&h0; o.y = *(uint32_t*)&h1;
                *(uint2*)(S16out + off) = o;
            }
            if (S32out2) *(float4*)&S32out2[off] = ns;
        }
    }
}

// ---- prep: fp32 -> fp16 for inputs and state ----
#define SPLIT_VECS (BB * KK / 4)

__global__ void split_kernel(const float* __restrict__ in, const float* __restrict__ st,
                             __half* __restrict__ a16, __half* __restrict__ s16)
{
    int t = blockIdx.x * blockDim.x + threadIdx.x;
    if (t >= SPLIT_VECS) return;
    size_t i = (size_t)t * 4;
    float4 vi = *(const float4*)&in[i];
    float4 vs = *(const float4*)&st[i];
    __half2 a0, a1, s0, s1;
    a0.x = __float2half(vi.x); a0.y = __float2half(vi.y);
    a1.x = __float2half(vi.z); a1.y = __float2half(vi.w);
    s0.x = __float2half(vs.x); s0.y = __float2half(vs.y);
    s1.x = __float2half(vs.z); s1.y = __float2half(vs.w);
    *(__half2*)(a16 + i)     = a0;
    *(__half2*)(a16 + i + 2) = a1;
    *(__half2*)(s16 + i)     = s0;
    *(__half2*)(s16 + i + 2) = s1;
}

// ---- prep: transpose W -> Wt[n][k] fp16 (both halves) ----
__global__ void wprep_kernel(const float* __restrict__ W,
                             __half* __restrict__ WtIn, __half* __restrict__ WtRec)
{
    int t = blockIdx.x * blockDim.x + threadIdx.x;
    if (t >= NN * KK) return;
    int k = t / NN, n = t % NN;
    int h = blockIdx.y;
    float v = W[(size_t)(k + h * KK) * NN + n];
    size_t o = (size_t)n * KK + k;
    if (h == 0) WtIn[o]  = __float2half(v);
    else        WtRec[o] = __float2half(v);
}

extern "C" void kernel_launch(void* const* d_in, const int* in_sizes, int n_in,
                              void* d_out, int out_size)
{
    const float* inputs = (const float*)d_in[0];
    const float* state  = (const float*)d_in[1];
    const float* W      = (const float*)d_in[2];
    const float* bias   = (const float*)d_in[3];
    float* out = (float*)d_out;
    float* out2 = (out_size >= 2 * BB * NN) ? (out + (size_t)BB * NN) : nullptr;

    __half *a16, *s16_0, *s16_1, *wtin, *wtrec, *p16;
    float *s32_0, *s32_1;
    cudaGetSymbolAddress((void**)&a16,   g_A16);
    cudaGetSymbolAddress((void**)&s16_0, g_S16);  s16_1 = s16_0 + (size_t)BB * NN;
    cudaGetSymbolAddress((void**)&s32_0, g_S32);  s32_1 = s32_0 + (size_t)BB * NN;
    cudaGetSymbolAddress((void**)&p16,   g_P16);
    cudaGetSymbolAddress((void**)&wtin,  g_WtIn16);
    cudaGetSymbolAddress((void**)&wtrec, g_WtRec16);

    cudaFuncSetAttribute(ctrnn_hmma, cudaFuncAttributeMaxDynamicSharedMemorySize, DSMEM);

    split_kernel<<<(SPLIT_VECS + 255) / 256, 256>>>(inputs, state, a16, s16_0);
    wprep_kernel<<<dim3((NN * KK + 255) / 256, 2), 256>>>(W, wtin, wtrec);

    dim3 grid(NN / TN, BB / TM);   // (4, 64) = 256 CTAs

    // P16 = fp16(inputs @ W_in + bias)
    ctrnn_hmma<<<grid, 256, DSMEM>>>(a16, wtin, nullptr, nullptr, bias, p16,
                                     nullptr, nullptr, nullptr, 0);
    // 6 unfolds: fp16 operand ping-pong, fp32 state ping-pong
    ctrnn_hmma<<<grid, 256, DSMEM>>>(s16_0, wtrec, p16, state, nullptr, nullptr,
                                     s16_1, s32_0, nullptr, 1);
    ctrnn_hmma<<<grid, 256, DSMEM>>>(s16_1, wtrec, p16, s32_0, nullptr, nullptr,
                                     s16_0, s32_1, nullptr, 1);
    ctrnn_hmma<<<grid, 256, DSMEM>>>(s16_0, wtrec, p16, s32_1, nullptr, nullptr,
                                     s16_1, s32_0, nullptr, 1);
    ctrnn_hmma<<<grid, 256, DSMEM>>>(s16_1, wtrec, p16, s32_0, nullptr, nullptr,
                                     s16_0, s32_1, nullptr, 1);
    ctrnn_hmma<<<grid, 256, DSMEM>>>(s16_0, wtrec, p16, s32_1, nullptr, nullptr,
                                     s16_1, s32_0, nullptr, 1);
    // final unfold: no fp16 shadow needed
    ctrnn_hmma<<<grid, 256, DSMEM>>>(s16_1, wtrec, p16, s32_0, nullptr, nullptr,
                                     nullptr, out, out2, 1);
}

// round 13
// speedup vs baseline: 1.1446x; 1.0241x over previous
#include <cuda_runtime.h>
#include <cuda_fp16.h>
#include <math.h>
#include <stdint.h>

// CTRNN B=8192, N=512, K=512, 6 unfolds + 1 precompute GEMM.
// R13: R12 + tanh.approx.f32 (MUFU.TANH, single-op) replacing libm tanhf.
//   R12 analysis: epilogue tail is MUFU-throughput bound (~23us/launch of
//   transcendental work with libm tanhf). approx tanh cuts it ~3x.
// Geometry: CTA 128x128, warp 64x32, 2 CTAs/SM, 3-stage cp.async ring,
// K-chunk 64 (128B rows, XOR swizzle), smem-staged coalesced epilogue.

#define BB 8192
#define NN 512
#define KK 512

// ---- scratch (device globals; no allocs allowed) ----
__device__ __half g_A16[BB * KK];        // fp16(inputs)
__device__ __half g_S16[2][BB * NN];     // fp16 state operand (ping-pong)
__device__ float  g_S32[2][BB * NN];     // fp32 state (ping-pong)
__device__ __half g_P16[BB * NN];        // fp16 P
__device__ __half g_WtIn16[NN * KK];     // Wt[n][k] = W[k][n]
__device__ __half g_WtRec16[NN * KK];    // Wt[n][k] = W[k+512][n]

// ---- helpers ----
__device__ __forceinline__ uint32_t smem_u32(const void* p) {
    uint32_t a;
    asm("{ .reg .u64 t; cvta.to.shared.u64 t, %1; cvt.u32.u64 %0, t; }" : "=r"(a) : "l"(p));
    return a;
}
__device__ __forceinline__ void cp_async16(uint32_t dst, const void* src) {
    asm volatile("cp.async.cg.shared.global [%0], [%1], 16;" :: "r"(dst), "l"(src));
}
#define CP_COMMIT() asm volatile("cp.async.commit_group;" ::: "memory")
#define CP_WAIT1()  asm volatile("cp.async.wait_group 1;" ::: "memory")
#define CP_WAIT0()  asm volatile("cp.async.wait_group 0;" ::: "memory")

__device__ __forceinline__ float tanh_approx(float x) {
    float y;
    asm("tanh.approx.f32 %0, %1;" : "=f"(y) : "f"(x));
    return y;
}
__device__ __forceinline__ void ldm4(uint32_t* r, uint32_t addr) {
    asm volatile("ldmatrix.sync.aligned.m8n8.x4.shared.b16 {%0,%1,%2,%3}, [%4];"
                 : "=r"(r[0]), "=r"(r[1]), "=r"(r[2]), "=r"(r[3]) : "r"(addr));
}
__device__ __forceinline__ void mma16816(float* d, const uint32_t* a, uint32_t b0, uint32_t b1) {
    asm volatile(
        "mma.sync.aligned.m16n8k16.row.col.f32.f16.f16.f32 "
        "{%0,%1,%2,%3}, {%4,%5,%6,%7}, {%8,%9}, {%0,%1,%2,%3};"
        : "+f"(d[0]), "+f"(d[1]), "+f"(d[2]), "+f"(d[3])
        : "r"(a[0]), "r"(a[1]), "r"(a[2]), "r"(a[3]), "r"(b0), "r"(b1));
}

// ---- geometry ----
#define TM 128
#define TN 128
#define TKC 64                 // K-chunk (fp16) = 128B rows
#define NCHUNK (KK / TKC)      // 8
#define NSTAGE 3
#define TILE_SZ (128 * 128)    // 16384 bytes (A or B tile)
#define BUF_B (2 * TILE_SZ)    // 32768 (A then B)
#define STG_STRIDE 132         // floats per staged row (pad vs bank conflicts)
#define DSMEM_MAIN (NSTAGE * BUF_B)              // 98304
#define DSMEM_STG  (TM * STG_STRIDE * 4)         // 67584
#define DSMEM (DSMEM_MAIN > DSMEM_STG ? DSMEM_MAIN : DSMEM_STG)

// fill a 128-row x 64-fp16 tile (128B swizzled rows) from [row0..][kc..kc+64)
__device__ __forceinline__ void fill_tile(uint32_t sbase, const __half* g,
                                          int row0, int kc, int tid) {
    #pragma unroll
    for (int c = tid; c < 1024; c += 256) {      // 1024 16B chunks
        int r = c >> 3, q = c & 7;
        uint32_t dst = sbase + (uint32_t)(r * 128 + ((q ^ (r & 7)) * 16));
        cp_async16(dst, g + (size_t)(row0 + r) * 512 + kc + q * 8);
    }
}

__global__ __launch_bounds__(256, 2)
void ctrnn_hmma(const __half* __restrict__ A16,     // GEMM operand [8192,512] fp16
                const __half* __restrict__ Wt16,    // Wt [N][K] fp16
                const __half* __restrict__ P16,     // mode1 in (fp16 P)
                const float* __restrict__ S32in,    // mode1 in (fp32 state)
                const float* __restrict__ bias,     // mode0 in
                __half* __restrict__ P16out,        // mode0 out
                __half* __restrict__ S16out,        // mode1 out (fp16 shadow; may be null)
                float* __restrict__ S32out,         // mode1 out (fp32 state)
                float* __restrict__ S32out2,        // optional dup
                int mode)
{
    extern __shared__ char dsm_raw[];
    const uint32_t dsm = smem_u32(dsm_raw);
    float* const stg = (float*)dsm_raw;

    const int tid = threadIdx.x;
    const int w = tid >> 5;
    const int lane = tid & 31;
    const int warpM = w >> 2;        // 0..1 (64 rows each)
    const int warpN = w & 3;         // 0..3 (32 cols each)
    const int br = blockIdx.y * TM;
    const int bc = blockIdx.x * TN;

    float acc[4][4][4];
    #pragma unroll
    for (int mi = 0; mi < 4; mi++)
        #pragma unroll
        for (int ni = 0; ni < 4; ni++)
            #pragma unroll
            for (int q = 0; q < 4; q++) acc[mi][ni][q] = 0.0f;

    // per-lane swizzled ldmatrix base offsets (k16 group g => XOR g*32)
    uint32_t abase[4], bbase[2];
    {
        const int arl = lane & 15, aq = lane >> 4;
        #pragma unroll
        for (int mi = 0; mi < 4; mi++) {
            int row = warpM * 64 + mi * 16 + arl;
            abase[mi] = (uint32_t)(row * 128 + ((aq ^ (row & 7)) * 16));
        }
        const int brl = (lane >> 4) * 8 + (lane & 7), bq = (lane >> 3) & 1;
        #pragma unroll
        for (int p = 0; p < 2; p++) {
            int row = warpN * 32 + p * 16 + brl;
            bbase[p] = (uint32_t)(row * 128 + ((bq ^ (row & 7)) * 16));
        }
    }

    // prologue: fill stages 0,1 (chunks 0,1)
    #pragma unroll
    for (int s = 0; s < 2; s++) {
        uint32_t sb = dsm + s * BUF_B;
        fill_tile(sb,           A16,  br, s * TKC, tid);
        fill_tile(sb + TILE_SZ, Wt16, bc, s * TKC, tid);
        CP_COMMIT();
    }

    int stage = 0, fstage = 2;
    for (int i = 0; i < NCHUNK; i++) {
        if (i == NCHUNK - 1) { CP_WAIT0(); } else { CP_WAIT1(); }
        __syncthreads();     // also guards reuse of stage fstage
        if (i + 2 < NCHUNK) {
            uint32_t nb = dsm + fstage * BUF_B;
            fill_tile(nb,           A16,  br, (i + 2) * TKC, tid);
            fill_tile(nb + TILE_SZ, Wt16, bc, (i + 2) * TKC, tid);
            CP_COMMIT();
        }

        const uint32_t sb = dsm + stage * BUF_B;
        #pragma unroll
        for (int g = 0; g < 4; g++) {
            const uint32_t kx = (uint32_t)(g * 32);
            uint32_t a[4][4], b[2][4];
            #pragma unroll
            for (int mi = 0; mi < 4; mi++)
                ldm4(a[mi], (sb + abase[mi]) ^ kx);
            #pragma unroll
            for (int p = 0; p < 2; p++)
                ldm4(b[p], (sb + TILE_SZ + bbase[p]) ^ kx);
            #pragma unroll
            for (int mi = 0; mi < 4; mi++)
                #pragma unroll
                for (int ni = 0; ni < 4; ni++) {
                    const uint32_t* B = b[ni >> 1];
                    const int o = (ni & 1) * 2;
                    mma16816(acc[mi][ni], a[mi], B[o], B[o + 1]);
                }
        }
        stage = (stage + 1 == NSTAGE) ? 0 : stage + 1;
        fstage = (fstage + 1 == NSTAGE) ? 0 : fstage + 1;
    }

    // ---- epilogue: stage acc to smem, then coalesced linear pass ----
    __syncthreads();   // mainloop smem reads complete before overwrite

    const int tg = lane >> 2;        // 0..7
    const int tp = lane & 3;         // 0..3
    #pragma unroll
    for (int mi = 0; mi < 4; mi++) {
        #pragma unroll
        for (int h = 0; h < 2; h++) {
            const int r = warpM * 64 + mi * 16 + tg + h * 8;
            #pragma unroll
            for (int ni = 0; ni < 4; ni++) {
                const int c = warpN * 32 + ni * 8 + tp * 2;
                *(float2*)&stg[r * STG_STRIDE + c] =
                    make_float2(acc[mi][ni][h * 2 + 0], acc[mi][ni][h * 2 + 1]);
            }
        }
    }
    __syncthreads();

    // linear pass: 16384 elems = 4096 float4 chunks; 16 per thread.
    #pragma unroll
    for (int it = 0; it < 16; it++) {
        const int idx = it * 256 + tid;
        const int r = idx >> 5;                // 32 chunks per row
        const int cq = (idx & 31) * 4;
        const float4 v = *(const float4*)&stg[r * STG_STRIDE + cq];
        const size_t off = (size_t)(br + r) * NN + bc + cq;

        if (mode == 0) {
            float4 bv = *(const float4*)&bias[bc + cq];
            __half2 h0, h1;
            h0.x = __float2half(v.x + bv.x); h0.y = __float2half(v.y + bv.y);
            h1.x = __float2half(v.z + bv.z); h1.y = __float2half(v.w + bv.w);
            uint2 o;
            o.x = *(uint32_t*)&h0; o.y = *(uint32_t*)&h1;
            *(uint2*)(P16out + off) = o;
        } else {
            uint2 praw = *(const uint2*)(P16 + off);
            __half2 p0 = *(__half2*)&praw.x, p1 = *(__half2*)&praw.y;
            float4 sv = *(const float4*)&S32in[off];
            float f0 = tanh_approx(__half2float(p0.x) + v.x);
            float f1 = tanh_approx(__half2float(p0.y) + v.y);
            float f2 = tanh_approx(__half2float(p1.x) + v.z);
            float f3 = tanh_approx(__half2float(p1.y) + v.w);
            float4 ns;
            ns.x = sv.x + 0.1f * (f0 - sv.x);
            ns.y = sv.y + 0.1f * (f1 - sv.y);
            ns.z = sv.z + 0.1f * (f2 - sv.z);
            ns.w = sv.w + 0.1f * (f3 - sv.w);
            *(float4*)&S32out[off] = ns;
            if (S16out) {
                __half2 h0, h1;
                h0.x = __float2half(ns.x); h0.y = __float2half(ns.y);
                h1.x = __float2half(ns.z); h1.y = __float2half(ns.w);
                uint2 o;
                o.x = *(uint32_t*)&h0; o.y = *(uint32_t*)&h1;
                *(uint2*)(S16out + off) = o;
            }
            if (S32out2) *(float4*)&S32out2[off] = ns;
        }
    }
}

// ---- prep: fp32 -> fp16 for inputs and state ----
#define SPLIT_VECS (BB * KK / 4)

__global__ void split_kernel(const float* __restrict__ in, const float* __restrict__ st,
                             __half* __restrict__ a16, __half* __restrict__ s16)
{
    int t = blockIdx.x * blockDim.x + threadIdx.x;
    if (t >= SPLIT_VECS) return;
    size_t i = (size_t)t * 4;
    float4 vi = *(const float4*)&in[i];
    float4 vs = *(const float4*)&st[i];
    __half2 a0, a1, s0, s1;
    a0.x = __float2half(vi.x); a0.y = __float2half(vi.y);
    a1.x = __float2half(vi.z); a1.y = __float2half(vi.w);
    s0.x = __float2half(vs.x); s0.y = __float2half(vs.y);
    s1.x = __float2half(vs.z); s1.y = __float2half(vs.w);
    *(__half2*)(a16 + i)     = a0;
    *(__half2*)(a16 + i + 2) = a1;
    *(__half2*)(s16 + i)     = s0;
    *(__half2*)(s16 + i + 2) = s1;
}

// ---- prep: transpose W -> Wt[n][k] fp16 (both halves) ----
__global__ void wprep_kernel(const float* __restrict__ W,
                             __half* __restrict__ WtIn, __half* __restrict__ WtRec)
{
    int t = blockIdx.x * blockDim.x + threadIdx.x;
    if (t >= NN * KK) return;
    int k = t / NN, n = t % NN;
    int h = blockIdx.y;
    float v = W[(size_t)(k + h * KK) * NN + n];
    size_t o = (size_t)n * KK + k;
    if (h == 0) WtIn[o]  = __float2half(v);
    else        WtRec[o] = __float2half(v);
}

extern "C" void kernel_launch(void* const* d_in, const int* in_sizes, int n_in,
                              void* d_out, int out_size)
{
    const float* inputs = (const float*)d_in[0];
    const float* state  = (const float*)d_in[1];
    const float* W      = (const float*)d_in[2];
    const float* bias   = (const float*)d_in[3];
    float* out = (float*)d_out;
    float* out2 = (out_size >= 2 * BB * NN) ? (out + (size_t)BB * NN) : nullptr;

    __half *a16, *s16_0, *s16_1, *wtin, *wtrec, *p16;
    float *s32_0, *s32_1;
    cudaGetSymbolAddress((void**)&a16,   g_A16);
    cudaGetSymbolAddress((void**)&s16_0, g_S16);  s16_1 = s16_0 + (size_t)BB * NN;
    cudaGetSymbolAddress((void**)&s32_0, g_S32);  s32_1 = s32_0 + (size_t)BB * NN;
    cudaGetSymbolAddress((void**)&p16,   g_P16);
    cudaGetSymbolAddress((void**)&wtin,  g_WtIn16);
    cudaGetSymbolAddress((void**)&wtrec, g_WtRec16);

    cudaFuncSetAttribute(ctrnn_hmma, cudaFuncAttributeMaxDynamicSharedMemorySize, DSMEM);

    split_kernel<<<(SPLIT_VECS + 255) / 256, 256>>>(inputs, state, a16, s16_0);
    wprep_kernel<<<dim3((NN * KK + 255) / 256, 2), 256>>>(W, wtin, wtrec);

    dim3 grid(NN / TN, BB / TM);   // (4, 64) = 256 CTAs

    // P16 = fp16(inputs @ W_in + bias)
    ctrnn_hmma<<<grid, 256, DSMEM>>>(a16, wtin, nullptr, nullptr, bias, p16,
                                     nullptr, nullptr, nullptr, 0);
    // 6 unfolds: fp16 operand ping-pong, fp32 state ping-pong
    ctrnn_hmma<<<grid, 256, DSMEM>>>(s16_0, wtrec, p16, state, nullptr, nullptr,
                                     s16_1, s32_0, nullptr, 1);
    ctrnn_hmma<<<grid, 256, DSMEM>>>(s16_1, wtrec, p16, s32_0, nullptr, nullptr,
                                     s16_0, s32_1, nullptr, 1);
    ctrnn_hmma<<<grid, 256, DSMEM>>>(s16_0, wtrec, p16, s32_1, nullptr, nullptr,
                                     s16_1, s32_0, nullptr, 1);
    ctrnn_hmma<<<grid, 256, DSMEM>>>(s16_1, wtrec, p16, s32_0, nullptr, nullptr,
                                     s16_0, s32_1, nullptr, 1);
    ctrnn_hmma<<<grid, 256, DSMEM>>>(s16_0, wtrec, p16, s32_1, nullptr, nullptr,
                                     s16_1, s32_0, nullptr, 1);
    // final unfold: no fp16 shadow needed
    ctrnn_hmma<<<grid, 256, DSMEM>>>(s16_1, wtrec, p16, s32_0, nullptr, nullptr,
                                     nullptr, out, out2, 1);
}

// round 14
// speedup vs baseline: 1.1561x; 1.0101x over previous
#include <cuda_runtime.h>
#include <cuda_fp16.h>
#include <math.h>
#include <stdint.h>

// CTRNN B=8192, N=512, K=512, 6 unfolds + 1 precompute GEMM.
// R13: R12 + tanh.approx.f32 (MUFU.TANH, single-op) replacing libm tanhf.
//   R12 analysis: epilogue tail is MUFU-throughput bound (~23us/launch of
//   transcendental work with libm tanhf). approx tanh cuts it ~3x.
// Geometry: CTA 128x128, warp 64x32, 2 CTAs/SM, 3-stage cp.async ring,
// K-chunk 64 (128B rows, XOR swizzle), smem-staged coalesced epilogue.

#define BB 8192
#define NN 512
#define KK 512

// ---- scratch (device globals; no allocs allowed) ----
__device__ __half g_A16[BB * KK];        // fp16(inputs)
__device__ __half g_S16[2][BB * NN];     // fp16 state operand (ping-pong)
__device__ float  g_S32[2][BB * NN];     // fp32 state (ping-pong)
__device__ __half g_P16[BB * NN];        // fp16 P
__device__ __half g_WtIn16[NN * KK];     // Wt[n][k] = W[k][n]
__device__ __half g_WtRec16[NN * KK];    // Wt[n][k] = W[k+512][n]

// ---- helpers ----
__device__ __forceinline__ uint32_t smem_u32(const void* p) {
    uint32_t a;
    asm("{ .reg .u64 t; cvta.to.shared.u64 t, %1; cvt.u32.u64 %0, t; }" : "=r"(a) : "l"(p));
    return a;
}
__device__ __forceinline__ void cp_async16(uint32_t dst, const void* src) {
    asm volatile("cp.async.cg.shared.global [%0], [%1], 16;" :: "r"(dst), "l"(src));
}
#define CP_COMMIT() asm volatile("cp.async.commit_group;" ::: "memory")
#define CP_WAIT1()  asm volatile("cp.async.wait_group 1;" ::: "memory")
#define CP_WAIT0()  asm volatile("cp.async.wait_group 0;" ::: "memory")

__device__ __forceinline__ float tanh_approx(float x) {
    float y;
    asm("tanh.approx.f32 %0, %1;" : "=f"(y) : "f"(x));
    return y;
}
__device__ __forceinline__ void ldm4(uint32_t* r, uint32_t addr) {
    asm volatile("ldmatrix.sync.aligned.m8n8.x4.shared.b16 {%0,%1,%2,%3}, [%4];"
                 : "=r"(r[0]), "=r"(r[1]), "=r"(r[2]), "=r"(r[3]) : "r"(addr));
}
__device__ __forceinline__ void mma16816(float* d, const uint32_t* a, uint32_t b0, uint32_t b1) {
    asm volatile(
        "mma.sync.aligned.m16n8k16.row.col.f32.f16.f16.f32 "
        "{%0,%1,%2,%3}, {%4,%5,%6,%7}, {%8,%9}, {%0,%1,%2,%3};"
        : "+f"(d[0]), "+f"(d[1]), "+f"(d[2]), "+f"(d[3])
        : "r"(a[0]), "r"(a[1]), "r"(a[2]), "r"(a[3]), "r"(b0), "r"(b1));
}

// ---- geometry ----
#define TM 128
#define TN 128
#define TKC 64                 // K-chunk (fp16) = 128B rows
#define NCHUNK (KK / TKC)      // 8
#define NSTAGE 3
#define TILE_SZ (128 * 128)    // 16384 bytes (A or B tile)
#define BUF_B (2 * TILE_SZ)    // 32768 (A then B)
#define STG_STRIDE 132         // floats per staged row (pad vs bank conflicts)
#define DSMEM_MAIN (NSTAGE * BUF_B)              // 98304
#define DSMEM_STG  (TM * STG_STRIDE * 4)         // 67584
#define DSMEM (DSMEM_MAIN > DSMEM_STG ? DSMEM_MAIN : DSMEM_STG)

// fill a 128-row x 64-fp16 tile (128B swizzled rows) from [row0..][kc..kc+64)
__device__ __forceinline__ void fill_tile(uint32_t sbase, const __half* g,
                                          int row0, int kc, int tid) {
    #pragma unroll
    for (int c = tid; c < 1024; c += 256) {      // 1024 16B chunks
        int r = c >> 3, q = c & 7;
        uint32_t dst = sbase + (uint32_t)(r * 128 + ((q ^ (r & 7)) * 16));
        cp_async16(dst, g + (size_t)(row0 + r) * 512 + kc + q * 8);
    }
}

__global__ __launch_bounds__(256, 2)
void ctrnn_hmma(const __half* __restrict__ A16,     // GEMM operand [8192,512] fp16
                const __half* __restrict__ Wt16,    // Wt [N][K] fp16
                const __half* __restrict__ P16,     // mode1 in (fp16 P)
                const float* __restrict__ S32in,    // mode1 in (fp32 state)
                const float* __restrict__ bias,     // mode0 in
                __half* __restrict__ P16out,        // mode0 out
                __half* __restrict__ S16out,        // mode1 out (fp16 shadow; may be null)
                float* __restrict__ S32out,         // mode1 out (fp32 state)
                float* __restrict__ S32out2,        // optional dup
                int mode)
{
    extern __shared__ char dsm_raw[];
    const uint32_t dsm = smem_u32(dsm_raw);
    float* const stg = (float*)dsm_raw;

    const int tid = threadIdx.x;
    const int w = tid >> 5;
    const int lane = tid & 31;
    const int warpM = w >> 2;        // 0..1 (64 rows each)
    const int warpN = w & 3;         // 0..3 (32 cols each)
    const int br = blockIdx.y * TM;
    const int bc = blockIdx.x * TN;

    float acc[4][4][4];
    #pragma unroll
    for (int mi = 0; mi < 4; mi++)
        #pragma unroll
        for (int ni = 0; ni < 4; ni++)
            #pragma unroll
            for (int q = 0; q < 4; q++) acc[mi][ni][q] = 0.0f;

    // per-lane swizzled ldmatrix base offsets (k16 group g => XOR g*32)
    uint32_t abase[4], bbase[2];
    {
        const int arl = lane & 15, aq = lane >> 4;
        #pragma unroll
        for (int mi = 0; mi < 4; mi++) {
            int row = warpM * 64 + mi * 16 + arl;
            abase[mi] = (uint32_t)(row * 128 + ((aq ^ (row & 7)) * 16));
        }
        const int brl = (lane >> 4) * 8 + (lane & 7), bq = (lane >> 3) & 1;
        #pragma unroll
        for (int p = 0; p < 2; p++) {
            int row = warpN * 32 + p * 16 + brl;
            bbase[p] = (uint32_t)(row * 128 + ((bq ^ (row & 7)) * 16));
        }
    }

    // prologue: fill stages 0,1 (chunks 0,1)
    #pragma unroll
    for (int s = 0; s < 2; s++) {
        uint32_t sb = dsm + s * BUF_B;
        fill_tile(sb,           A16,  br, s * TKC, tid);
        fill_tile(sb + TILE_SZ, Wt16, bc, s * TKC, tid);
        CP_COMMIT();
    }

    int stage = 0, fstage = 2;
    for (int i = 0; i < NCHUNK; i++) {
        if (i == NCHUNK - 1) { CP_WAIT0(); } else { CP_WAIT1(); }
        __syncthreads();     // also guards reuse of stage fstage
        if (i + 2 < NCHUNK) {
            uint32_t nb = dsm + fstage * BUF_B;
            fill_tile(nb,           A16,  br, (i + 2) * TKC, tid);
            fill_tile(nb + TILE_SZ, Wt16, bc, (i + 2) * TKC, tid);
            CP_COMMIT();
        }

        const uint32_t sb = dsm + stage * BUF_B;
        #pragma unroll
        for (int g = 0; g < 4; g++) {
            const uint32_t kx = (uint32_t)(g * 32);
            uint32_t a[4][4], b[2][4];
            #pragma unroll
            for (int mi = 0; mi < 4; mi++)
                ldm4(a[mi], (sb + abase[mi]) ^ kx);
            #pragma unroll
            for (int p = 0; p < 2; p++)
                ldm4(b[p], (sb + TILE_SZ + bbase[p]) ^ kx);
            #pragma unroll
            for (int mi = 0; mi < 4; mi++)
                #pragma unroll
                for (int ni = 0; ni < 4; ni++) {
                    const uint32_t* B = b[ni >> 1];
                    const int o = (ni & 1) * 2;
                    mma16816(acc[mi][ni], a[mi], B[o], B[o + 1]);
                }
        }
        stage = (stage + 1 == NSTAGE) ? 0 : stage + 1;
        fstage = (fstage + 1 == NSTAGE) ? 0 : fstage + 1;
    }

    // ---- epilogue: stage acc to smem, then coalesced linear pass ----
    __syncthreads();   // mainloop smem reads complete before overwrite

    const int tg = lane >> 2;        // 0..7
    const int tp = lane & 3;         // 0..3
    #pragma unroll
    for (int mi = 0; mi < 4; mi++) {
        #pragma unroll
        for (int h = 0; h < 2; h++) {
            const int r = warpM * 64 + mi * 16 + tg + h * 8;
            #pragma unroll
            for (int ni = 0; ni < 4; ni++) {
                const int c = warpN * 32 + ni * 8 + tp * 2;
                *(float2*)&stg[r * STG_STRIDE + c] =
                    make_float2(acc[mi][ni][h * 2 + 0], acc[mi][ni][h * 2 + 1]);
            }
        }
    }
    __syncthreads();

    // linear pass: 16384 elems = 4096 float4 chunks; 16 per thread.
    #pragma unroll
    for (int it = 0; it < 16; it++) {
        const int idx = it * 256 + tid;
        const int r = idx >> 5;                // 32 chunks per row
        const int cq = (idx & 31) * 4;
        const float4 v = *(const float4*)&stg[r * STG_STRIDE + cq];
        const size_t off = (size_t)(br + r) * NN + bc + cq;

        if (mode == 0) {
            float4 bv = *(const float4*)&bias[bc + cq];
            __half2 h0, h1;
            h0.x = __float2half(v.x + bv.x); h0.y = __float2half(v.y + bv.y);
            h1.x = __float2half(v.z + bv.z); h1.y = __float2half(v.w + bv.w);
            uint2 o;
            o.x = *(uint32_t*)&h0; o.y = *(uint32_t*)&h1;
            *(uint2*)(P16out + off) = o;
        } else {
            uint2 praw = *(const uint2*)(P16 + off);
            __half2 p0 = *(__half2*)&praw.x, p1 = *(__half2*)&praw.y;
            float4 sv = *(const float4*)&S32in[off];
            float f0 = tanh_approx(__half2float(p0.x) + v.x);
            float f1 = tanh_approx(__half2float(p0.y) + v.y);
            float f2 = tanh_approx(__half2float(p1.x) + v.z);
            float f3 = tanh_approx(__half2float(p1.y) + v.w);
            float4 ns;
            ns.x = sv.x + 0.1f * (f0 - sv.x);
            ns.y = sv.y + 0.1f * (f1 - sv.y);
            ns.z = sv.z + 0.1f * (f2 - sv.z);
            ns.w = sv.w + 0.1f * (f3 - sv.w);
            *(float4*)&S32out[off] = ns;
            if (S16out) {
                __half2 h0, h1;
                h0.x = __float2half(ns.x); h0.y = __float2half(ns.y);
                h1.x = __float2half(ns.z); h1.y = __float2half(ns.w);
                uint2 o;
                o.x = *(uint32_t*)&h0; o.y = *(uint32_t*)&h1;
                *(uint2*)(S16out + off) = o;
            }
            if (S32out2) *(float4*)&S32out2[off] = ns;
        }
    }
}

// ---- prep: fp32 -> fp16 for inputs and state ----
#define SPLIT_VECS (BB * KK / 4)

__global__ void split_kernel(const float* __restrict__ in, const float* __restrict__ st,
                             __half* __restrict__ a16, __half* __restrict__ s16)
{
    int t = blockIdx.x * blockDim.x + threadIdx.x;
    if (t >= SPLIT_VECS) return;
    size_t i = (size_t)t * 4;
    float4 vi = *(const float4*)&in[i];
    float4 vs = *(const float4*)&st[i];
    __half2 a0, a1, s0, s1;
    a0.x = __float2half(vi.x); a0.y = __float2half(vi.y);
    a1.x = __float2half(vi.z); a1.y = __float2half(vi.w);
    s0.x = __float2half(vs.x); s0.y = __float2half(vs.y);
    s1.x = __float2half(vs.z); s1.y = __float2half(vs.w);
    *(__half2*)(a16 + i)     = a0;
    *(__half2*)(a16 + i + 2) = a1;
    *(__half2*)(s16 + i)     = s0;
    *(__half2*)(s16 + i + 2) = s1;
}

// ---- prep: transpose W -> Wt[n][k] fp16 (both halves) ----
__global__ void wprep_kernel(const float* __restrict__ W,
                             __half* __restrict__ WtIn, __half* __restrict__ WtRec)
{
    int t = blockIdx.x * blockDim.x + threadIdx.x;
    if (t >= NN * KK) return;
    int k = t / NN, n = t % NN;
    int h = blockIdx.y;
    float v = W[(size_t)(k + h * KK) * NN + n];
    size_t o = (size_t)n * KK + k;
    if (h == 0) WtIn[o]  = __float2half(v);
    else        WtRec[o] = __float2half(v);
}

extern "C" void kernel_launch(void* const* d_in, const int* in_sizes, int n_in,
                              void* d_out, int out_size)
{
    const float* inputs = (const float*)d_in[0];
    const float* state  = (const float*)d_in[1];
    const float* W      = (const float*)d_in[2];
    const float* bias   = (const float*)d_in[3];
    float* out = (float*)d_out;
    float* out2 = (out_size >= 2 * BB * NN) ? (out + (size_t)BB * NN) : nullptr;

    __half *a16, *s16_0, *s16_1, *wtin, *wtrec, *p16;
    float *s32_0, *s32_1;
    cudaGetSymbolAddress((void**)&a16,   g_A16);
    cudaGetSymbolAddress((void**)&s16_0, g_S16);  s16_1 = s16_0 + (size_t)BB * NN;
    cudaGetSymbolAddress((void**)&s32_0, g_S32);  s32_1 = s32_0 + (size_t)BB * NN;
    cudaGetSymbolAddress((void**)&p16,   g_P16);
    cudaGetSymbolAddress((void**)&wtin,  g_WtIn16);
    cudaGetSymbolAddress((void**)&wtrec, g_WtRec16);

    cudaFuncSetAttribute(ctrnn_hmma, cudaFuncAttributeMaxDynamicSharedMemorySize, DSMEM);

    split_kernel<<<(SPLIT_VECS + 255) / 256, 256>>>(inputs, state, a16, s16_0);
    wprep_kernel<<<dim3((NN * KK + 255) / 256, 2), 256>>>(W, wtin, wtrec);

    dim3 grid(NN / TN, BB / TM);   // (4, 64) = 256 CTAs

    // P16 = fp16(inputs @ W_in + bias)
    ctrnn_hmma<<<grid, 256, DSMEM>>>(a16, wtin, nullptr, nullptr, bias, p16,
                                     nullptr, nullptr, nullptr, 0);
    // 6 unfolds: fp16 operand ping-pong, fp32 state ping-pong
    ctrnn_hmma<<<grid, 256, DSMEM>>>(s16_0, wtrec, p16, state, nullptr, nullptr,
                                     s16_1, s32_0, nullptr, 1);
    ctrnn_hmma<<<grid, 256, DSMEM>>>(s16_1, wtrec, p16, s32_0, nullptr, nullptr,
                                     s16_0, s32_1, nullptr, 1);
    ctrnn_hmma<<<grid, 256, DSMEM>>>(s16_0, wtrec, p16, s32_1, nullptr, nullptr,
                                     s16_1, s32_0, nullptr, 1);
    ctrnn_hmma<<<grid, 256, DSMEM>>>(s16_1, wtrec, p16, s32_0, nullptr, nullptr,
                                     s16_0, s32_1, nullptr, 1);
    ctrnn_hmma<<<grid, 256, DSMEM>>>(s16_0, wtrec, p16, s32_1, nullptr, nullptr,
                                     s16_1, s32_0, nullptr, 1);
    // final unfold: no fp16 shadow needed
    ctrnn_hmma<<<grid, 256, DSMEM>>>(s16_1, wtrec, p16, s32_0, nullptr, nullptr,
                                     nullptr, out, out2, 1);
}